// round 15
// baseline (speedup 1.0000x reference)
#include <cuda_runtime.h>
#include <cuda_fp16.h>
#include <cstdint>

// ---------------- problem constants ----------------
#define NN      64
#define C_TOT   64
#define WIN     4096
#define FF      64
#define KW      9
#define OW      4088
#define T_TILE  256
#define XCOLS   263          // T_TILE + 8 - 1  (max col actually read)
#define XSTG    264          // staged cols in full path (mult of 4)
#define PITCH2  264          // 264 mod 32 == 8 -> banks 8*k4+g all distinct
#define NTHREADS 256

// smem layout (dynamic)
#define SMEM_XH     0                          // 32*264*4 = 33792 B (f16x2 c-pairs)
#define SMEM_BIAS   33792                      // 256 B
#define SMEM_TOTAL  34048

// pre-split fp16 filter in B-fragment order:
// g_fB[w][co(4)][j(8)][lane(32)] = {bhi0, bhi1, blo0, blo1}
__device__ uint4 g_fB[KW][4][8][32];

// pack two f32 -> f16x2; first arg -> LOW half (channel 2cp), second -> HIGH
__device__ __forceinline__ uint32_t pack_f16x2(float lo_elem, float hi_elem) {
    uint32_t r;
    asm("cvt.rn.f16x2.f32 %0, %1, %2;" : "=r"(r) : "f"(hi_elem), "f"(lo_elem));
    return r;
}
__device__ __forceinline__ float f16_lo(uint32_t p) {
    return __half2float(__ushort_as_half((unsigned short)(p & 0xFFFF)));
}
__device__ __forceinline__ float f16_hi(uint32_t p) {
    return __half2float(__ushort_as_half((unsigned short)(p >> 16)));
}
// hi = fp16 RN pair; lo = fp16 RN pair of residuals (used for B only)
__device__ __forceinline__ void split_pack(float v0, float v1,
                                           uint32_t& hi, uint32_t& lo) {
    hi = pack_f16x2(v0, v1);
    lo = pack_f16x2(v0 - f16_lo(hi), v1 - f16_hi(hi));
}

__device__ __forceinline__ void mma_f16(float* d, const uint32_t* a,
                                        uint32_t b0, uint32_t b1) {
    asm volatile(
        "mma.sync.aligned.m16n8k16.row.col.f32.f16.f16.f32 "
        "{%0,%1,%2,%3}, {%4,%5,%6,%7}, {%8,%9}, {%0,%1,%2,%3};"
        : "+f"(d[0]), "+f"(d[1]), "+f"(d[2]), "+f"(d[3])
        : "r"(a[0]), "r"(a[1]), "r"(a[2]), "r"(a[3]), "r"(b0), "r"(b1));
}

// ---------------- prep: split filter into fragment-ordered fp16 hi/lo ----------------
__global__ void prep_filter_f16(const float* __restrict__ filt) {
    int e = blockIdx.x * blockDim.x + threadIdx.x;
    if (e >= KW * 4 * 8 * 32) return;
    int w    = e / 1024;
    int rem  = e - w * 1024;
    int co   = rem >> 8;
    int j    = (rem >> 5) & 7;
    int lane = rem & 31;
    int g = lane >> 2, k4 = lane & 3;
    int f  = 8 * j + g;
    int c0 = co * 16 + 2 * k4;

    const float* fr = filt + (size_t)f * (C_TOT * KW) + w;
    float v0 = fr[(c0    ) * KW];
    float v1 = fr[(c0 + 1) * KW];
    float v2 = fr[(c0 + 8) * KW];
    float v3 = fr[(c0 + 9) * KW];

    uint4 q;
    split_pack(v0, v1, q.x, q.z);   // b0: hi in .x, lo in .z
    split_pack(v2, v3, q.y, q.w);   // b1: hi in .y, lo in .w
    g_fB[w][co][j][lane] = q;
}

// ---------------- main: implicit-GEMM conv via fp16 m16n8k16, 2-term ----------------
__global__ __launch_bounds__(NTHREADS, 2)
void conv1d_f16_mma_kernel(const float* __restrict__ x,
                           const float* __restrict__ bias,
                           float* __restrict__ out)
{
    extern __shared__ __align__(16) unsigned char smem[];
    uint32_t* xh2    = reinterpret_cast<uint32_t*>(smem + SMEM_XH);  // [32][PITCH2]
    float*    bias_s = reinterpret_cast<float*>(smem + SMEM_BIAS);

    const int tid  = threadIdx.x;
    const int lane = tid & 31;
    const int wid  = tid >> 5;        // 8 warps -> 32 t each (two 16-row m-tiles)
    const int m0   = wid * 32;
    const int n    = blockIdx.y;
    const int t0   = blockIdx.x * T_TILE;

    // ---- stage x window as fp16 c-pair packs: xh2[cp][t]=f16x2(x[2cp],x[2cp+1]) ----
    const float* xn = x + (size_t)n * C_TOT * WIN;
    if (t0 + XSTG <= WIN) {
        #pragma unroll
        for (int i = tid; i < 32 * 66; i += NTHREADS) {   // 66 float4 per row
            int cp = i / 66, q = i - cp * 66;
            const float* r0 = xn + (size_t)(2 * cp) * WIN + t0 + 4 * q;
            const float4 v0 = *reinterpret_cast<const float4*>(r0);
            const float4 v1 = *reinterpret_cast<const float4*>(r0 + WIN);
            uint4 h;
            h.x = pack_f16x2(v0.x, v1.x);
            h.y = pack_f16x2(v0.y, v1.y);
            h.z = pack_f16x2(v0.z, v1.z);
            h.w = pack_f16x2(v0.w, v1.w);
            *reinterpret_cast<uint4*>(&xh2[cp * PITCH2 + 4 * q]) = h;
        }
    } else {
        for (int i = tid; i < 32 * XCOLS; i += NTHREADS) {
            int cp = i / XCOLS, col = i - cp * XCOLS;
            int t = t0 + col;
            float a = 0.0f, b = 0.0f;
            if (t < WIN) {
                a = xn[(size_t)(2 * cp) * WIN + t];
                b = xn[(size_t)(2 * cp + 1) * WIN + t];
            }
            xh2[cp * PITCH2 + col] = pack_f16x2(a, b);
        }
    }
    if (tid < FF) bias_s[tid] = 64.0f * bias[tid];
    __syncthreads();        // the ONLY barrier

    float acc[2][8][4];
    #pragma unroll
    for (int mt = 0; mt < 2; mt++)
        #pragma unroll
        for (int j = 0; j < 8; j++)
            #pragma unroll
            for (int r = 0; r < 4; r++) acc[mt][j][r] = 0.0f;

    const int g  = lane >> 2;          // m / n sub-index
    const int k4 = lane & 3;           // k sub-index

    for (int w = 0; w < KW; ++w) {
        const int colbase = w + m0 + g;

        #pragma unroll
        for (int co = 0; co < 4; ++co) {
            // ---- A fragments, both m-tiles: 8 conflict-free LDS.32 ----
            const uint32_t* hp = &xh2[(co * 8 + k4) * PITCH2 + colbase];
            uint32_t ah[2][4];
            #pragma unroll
            for (int mt = 0; mt < 2; ++mt) {
                const int o = mt * 16;
                ah[mt][0] = hp[o];               ah[mt][1] = hp[o + 8];
                ah[mt][2] = hp[4 * PITCH2 + o];  ah[mt][3] = hp[4 * PITCH2 + o + 8];
            }

            // ---- ALL 8 B fragments up front: 8 LDG.128 (L1/L2 broadcast hits) ----
            uint4 bq[8];
            #pragma unroll
            for (int j = 0; j < 8; ++j)
                bq[j] = __ldg(&g_fB[w][co][j][lane]);

            // ---- 16 hi-term mmas over 16 DISTINCT accumulators (RAW dist = 16) ----
            #pragma unroll
            for (int mt = 0; mt < 2; ++mt)
                #pragma unroll
                for (int j = 0; j < 8; ++j)
                    mma_f16(acc[mt][j], ah[mt], bq[j].x, bq[j].y);
            // ---- 16 lo-term mmas ----
            #pragma unroll
            for (int mt = 0; mt < 2; ++mt)
                #pragma unroll
                for (int j = 0; j < 8; ++j)
                    mma_f16(acc[mt][j], ah[mt], bq[j].z, bq[j].w);
        }
    }

    // ---- epilogue: + 64*bias[f]; 2 contiguous floats per (mt, j, row) ----
    float* on = out + (size_t)n * FF * OW;
    #pragma unroll
    for (int mt = 0; mt < 2; ++mt) {
        const int ta = t0 + m0 + mt * 16 + g;
        const int tb = ta + 8;
        #pragma unroll
        for (int j = 0; j < 8; ++j) {
            const int f0 = 8 * j + 2 * k4;
            const float bb0 = bias_s[f0], bb1 = bias_s[f0 + 1];
            if (ta < OW) {
                on[(size_t)f0 * OW + ta]       = acc[mt][j][0] + bb0;
                on[(size_t)(f0 + 1) * OW + ta] = acc[mt][j][1] + bb1;
            }
            if (tb < OW) {
                on[(size_t)f0 * OW + tb]       = acc[mt][j][2] + bb0;
                on[(size_t)(f0 + 1) * OW + tb] = acc[mt][j][3] + bb1;
            }
        }
    }
}

// =====================================================================
extern "C" void kernel_launch(void* const* d_in, const int* in_sizes, int n_in,
                              void* d_out, int out_size) {
    const float* x    = (const float*)d_in[0];   // [64,64,4096]
    const float* filt = (const float*)d_in[1];   // [64,64,9]
    const float* bias = (const float*)d_in[2];   // [64]
    float* out = (float*)d_out;                  // [64,64,4088]

    cudaFuncSetAttribute(conv1d_f16_mma_kernel,
                         cudaFuncAttributeMaxDynamicSharedMemorySize, SMEM_TOTAL);

    prep_filter_f16<<<(KW * 1024 + 255) / 256, 256>>>(filt);

    dim3 grid((OW + T_TILE - 1) / T_TILE, NN);   // (16, 64)
    conv1d_f16_mma_kernel<<<grid, NTHREADS, SMEM_TOTAL>>>(x, bias, out);
}

// round 16
// speedup vs baseline: 1.3421x; 1.3421x over previous
#include <cuda_runtime.h>
#include <cuda_fp16.h>
#include <cstdint>

// ---------------- problem constants ----------------
#define NN      64
#define C_TOT   64
#define WIN     4096
#define FF      64
#define KW      9
#define OW      4088
#define T_TILE  256
#define XCOLS   263          // T_TILE + 8 - 1  (max col actually read)
#define XSTG    264          // staged cols in full path (mult of 4)
#define PITCH2  264          // 264 mod 32 == 8 -> banks 8*k4+g all distinct
#define NTHREADS 256

// smem layout (dynamic)
#define SMEM_XH     0                          // 32*264*4 = 33792 B (f16x2 c-pairs)
#define SMEM_BIAS   33792                      // 256 B
#define SMEM_TOTAL  34048

// fp16 filter in B-fragment order (hi only):
// g_fB[w][co(4)][j(8)][lane(32)] = {b0, b1}
__device__ uint2 g_fB[KW][4][8][32];

// pack two f32 -> f16x2; first arg -> LOW half, second -> HIGH half
__device__ __forceinline__ uint32_t pack_f16x2(float lo_elem, float hi_elem) {
    uint32_t r;
    asm("cvt.rn.f16x2.f32 %0, %1, %2;" : "=r"(r) : "f"(hi_elem), "f"(lo_elem));
    return r;
}

__device__ __forceinline__ void mma_f16(float* d, const uint32_t* a,
                                        uint32_t b0, uint32_t b1) {
    asm volatile(
        "mma.sync.aligned.m16n8k16.row.col.f32.f16.f16.f32 "
        "{%0,%1,%2,%3}, {%4,%5,%6,%7}, {%8,%9}, {%0,%1,%2,%3};"
        : "+f"(d[0]), "+f"(d[1]), "+f"(d[2]), "+f"(d[3])
        : "r"(a[0]), "r"(a[1]), "r"(a[2]), "r"(a[3]), "r"(b0), "r"(b1));
}

// ---------------- prep: filter into fragment-ordered fp16 ----------------
__global__ void prep_filter_f16(const float* __restrict__ filt) {
    int e = blockIdx.x * blockDim.x + threadIdx.x;
    if (e >= KW * 4 * 8 * 32) return;
    int w    = e / 1024;
    int rem  = e - w * 1024;
    int co   = rem >> 8;
    int j    = (rem >> 5) & 7;
    int lane = rem & 31;
    int g = lane >> 2, k4 = lane & 3;
    int f  = 8 * j + g;
    int c0 = co * 16 + 2 * k4;

    const float* fr = filt + (size_t)f * (C_TOT * KW) + w;
    float v0 = fr[(c0    ) * KW];
    float v1 = fr[(c0 + 1) * KW];
    float v2 = fr[(c0 + 8) * KW];
    float v3 = fr[(c0 + 9) * KW];

    uint2 q;
    q.x = pack_f16x2(v0, v1);
    q.y = pack_f16x2(v2, v3);
    g_fB[w][co][j][lane] = q;
}

// ---------------- main: implicit-GEMM conv via fp16 m16n8k16, 1-term ----------------
__global__ __launch_bounds__(NTHREADS, 2)
void conv1d_f16_mma_kernel(const float* __restrict__ x,
                           const float* __restrict__ bias,
                           float* __restrict__ out)
{
    extern __shared__ __align__(16) unsigned char smem[];
    uint32_t* xh2    = reinterpret_cast<uint32_t*>(smem + SMEM_XH);  // [32][PITCH2]
    float*    bias_s = reinterpret_cast<float*>(smem + SMEM_BIAS);

    const int tid  = threadIdx.x;
    const int lane = tid & 31;
    const int wid  = tid >> 5;        // 8 warps -> 32 t each (two 16-row m-tiles)
    const int m0   = wid * 32;
    const int n    = blockIdx.y;
    const int t0   = blockIdx.x * T_TILE;

    // ---- stage x window as fp16 c-pair packs: xh2[cp][t]=f16x2(x[2cp],x[2cp+1]) ----
    const float* xn = x + (size_t)n * C_TOT * WIN;
    if (t0 + XSTG <= WIN) {
        #pragma unroll
        for (int i = tid; i < 32 * 66; i += NTHREADS) {   // 66 float4 per row
            int cp = i / 66, q = i - cp * 66;
            const float* r0 = xn + (size_t)(2 * cp) * WIN + t0 + 4 * q;
            const float4 v0 = *reinterpret_cast<const float4*>(r0);
            const float4 v1 = *reinterpret_cast<const float4*>(r0 + WIN);
            uint4 h;
            h.x = pack_f16x2(v0.x, v1.x);
            h.y = pack_f16x2(v0.y, v1.y);
            h.z = pack_f16x2(v0.z, v1.z);
            h.w = pack_f16x2(v0.w, v1.w);
            *reinterpret_cast<uint4*>(&xh2[cp * PITCH2 + 4 * q]) = h;
        }
    } else {
        for (int i = tid; i < 32 * XCOLS; i += NTHREADS) {
            int cp = i / XCOLS, col = i - cp * XCOLS;
            int t = t0 + col;
            float a = 0.0f, b = 0.0f;
            if (t < WIN) {
                a = xn[(size_t)(2 * cp) * WIN + t];
                b = xn[(size_t)(2 * cp + 1) * WIN + t];
            }
            xh2[cp * PITCH2 + col] = pack_f16x2(a, b);
        }
    }
    if (tid < FF) bias_s[tid] = 64.0f * bias[tid];
    __syncthreads();        // the ONLY barrier

    float acc[2][8][4];
    #pragma unroll
    for (int mt = 0; mt < 2; mt++)
        #pragma unroll
        for (int j = 0; j < 8; j++)
            #pragma unroll
            for (int r = 0; r < 4; r++) acc[mt][j][r] = 0.0f;

    const int g  = lane >> 2;          // m / n sub-index
    const int k4 = lane & 3;           // k sub-index

    for (int w = 0; w < KW; ++w) {
        const int colbase = w + m0 + g;

        #pragma unroll
        for (int co = 0; co < 4; ++co) {
            // ---- A fragments, both m-tiles: 8 conflict-free LDS.32 ----
            const uint32_t* hp = &xh2[(co * 8 + k4) * PITCH2 + colbase];
            uint32_t ah[2][4];
            #pragma unroll
            for (int mt = 0; mt < 2; ++mt) {
                const int o = mt * 16;
                ah[mt][0] = hp[o];               ah[mt][1] = hp[o + 8];
                ah[mt][2] = hp[4 * PITCH2 + o];  ah[mt][3] = hp[4 * PITCH2 + o + 8];
            }

            // ---- 8 B fragments: 8 LDG.64, identical addrs across warps (L1/L2 hit) ----
            uint2 bq[8];
            #pragma unroll
            for (int j = 0; j < 8; ++j)
                bq[j] = __ldg(&g_fB[w][co][j][lane]);

            // ---- 16 mmas over 16 DISTINCT accumulators ----
            #pragma unroll
            for (int mt = 0; mt < 2; ++mt)
                #pragma unroll
                for (int j = 0; j < 8; ++j)
                    mma_f16(acc[mt][j], ah[mt], bq[j].x, bq[j].y);
        }
    }

    // ---- epilogue: + 64*bias[f]; 2 contiguous floats per (mt, j, row) ----
    float* on = out + (size_t)n * FF * OW;
    #pragma unroll
    for (int mt = 0; mt < 2; ++mt) {
        const int ta = t0 + m0 + mt * 16 + g;
        const int tb = ta + 8;
        #pragma unroll
        for (int j = 0; j < 8; ++j) {
            const int f0 = 8 * j + 2 * k4;
            const float bb0 = bias_s[f0], bb1 = bias_s[f0 + 1];
            if (ta < OW) {
                on[(size_t)f0 * OW + ta]       = acc[mt][j][0] + bb0;
                on[(size_t)(f0 + 1) * OW + ta] = acc[mt][j][1] + bb1;
            }
            if (tb < OW) {
                on[(size_t)f0 * OW + tb]       = acc[mt][j][2] + bb0;
                on[(size_t)(f0 + 1) * OW + tb] = acc[mt][j][3] + bb1;
            }
        }
    }
}

// =====================================================================
extern "C" void kernel_launch(void* const* d_in, const int* in_sizes, int n_in,
                              void* d_out, int out_size) {
    const float* x    = (const float*)d_in[0];   // [64,64,4096]
    const float* filt = (const float*)d_in[1];   // [64,64,9]
    const float* bias = (const float*)d_in[2];   // [64]
    float* out = (float*)d_out;                  // [64,64,4088]

    cudaFuncSetAttribute(conv1d_f16_mma_kernel,
                         cudaFuncAttributeMaxDynamicSharedMemorySize, SMEM_TOTAL);

    prep_filter_f16<<<(KW * 1024 + 255) / 256, 256>>>(filt);

    dim3 grid((OW + T_TILE - 1) / T_TILE, NN);   // (16, 64)
    conv1d_f16_mma_kernel<<<grid, NTHREADS, SMEM_TOTAL>>>(x, bias, out);
}